// round 3
// baseline (speedup 1.0000x reference)
#include <cuda_runtime.h>
#include <math.h>

// One thread per antithetic pair: path A uses +Z, path B uses -Z.
// Z layout: [STEPS][2][NH] float32. Output: [2*NH] discounted payoffs.
//
// In-loop arithmetic mirrors XLA:GPU's LLVM "contract" FMA formation:
// fma exactly where a single-use mul feeds an add/sub; inner muls stay muls;
// no constant pre-folding. Constants & payoff use plain rn ops (HLO
// constant folding / eager dispatch does not form FMAs).

#define FMUL(a,b) __fmul_rn((a),(b))
#define FADD(a,b) __fadd_rn((a),(b))
#define FSUB(a,b) __fsub_rn((a),(b))
#define FMA(a,b,c) __fmaf_rn((a),(b),(c))

__global__ void __launch_bounds__(256, 8) cpl_mc_kernel(
    const float* __restrict__ x0,  const float* __restrict__ v0,
    const float* __restrict__ p10, const float* __restrict__ p20,
    const float* __restrict__ p30, const float* __restrict__ p40,
    const float* __restrict__ p50, const float* __restrict__ p60,
    const float* __restrict__ s_kappa,  const float* __restrict__ s_theta,
    const float* __restrict__ s_rho,    const float* __restrict__ s_sigma,
    const float* __restrict__ s_alpha0, const float* __restrict__ s_alpha1,
    const float* __restrict__ s_gamma,  const float* __restrict__ s_varphi,
    const float* __restrict__ s_strike, const float* __restrict__ s_delta,
    const float* __restrict__ s_notional, const float* __restrict__ s_dt,
    const float* __restrict__ Z,
    float* __restrict__ out, int NH, int STEPS)
{
    const int i = blockIdx.x * blockDim.x + threadIdx.x;
    if (i >= NH) return;

    // ---- scalars ----
    const float kappa  = *s_kappa;
    const float theta  = *s_theta;
    const float rho    = *s_rho;
    const float sigma  = *s_sigma;
    const float alpha0 = *s_alpha0;
    const float alpha1 = *s_alpha1;
    const float g      = *s_gamma;
    const float varphi = *s_varphi;
    const float strike = *s_strike;
    const float delta  = *s_delta;
    const float notional = *s_notional;
    const float dt     = *s_dt;

    // ---- derived constants: plain rn ops, exact reference order ----
    const float A  = FADD(__fdiv_rn(alpha0, g), __fdiv_rn(alpha1, FMUL(g, g)));
    const float Bc = __fdiv_rn(alpha1, g);
    const float sq1m = __fsqrt_rn(FSUB(1.0f, FMUL(rho, rho)));
    const float sqdt = __fsqrt_rn(dt);
    const float c5 = FADD(FMUL(alpha0, Bc), FMUL(alpha1, A));
    const float c6 = FMUL(alpha1, Bc);
    const float Aa0 = FMUL(A, alpha0);
    const float Aa1 = FMUL(A, alpha1);
    const float g2  = FMUL(2.0f, g);   // 2.0 * g (exact constant fold)

    // ---- state: path A (+Z) and path B (-Z) ----
    float xA = x0[i],  xB = xA;
    float vA = v0[i],  vB = vA;
    float p1A = p10[i], p1B = p1A;
    float p2A = p20[i], p2B = p2A;
    float p3A = p30[i], p3B = p3A;
    float p4A = p40[i], p4B = p4A;
    float p5A = p50[i], p5B = p5A;
    float p6A = p60[i], p6B = p6A;
    float irA = 0.0f,  irB = 0.0f;

    const size_t stride = (size_t)2 * (size_t)NH;
    const float* zv_ptr = Z + i;
    const float* zp_ptr = Z + (size_t)NH + i;

    #pragma unroll 4
    for (int t = 0; t < STEPS; ++t) {
        const float zv = __ldcs(zv_ptr);
        const float zp = __ldcs(zp_ptr);
        zv_ptr += stride;
        zp_ptr += stride;

        // dWv = sqdt*zv ; dWx = sqdt*(rho*zv + sq1m*zp)
        //   inner add(mul,mul) -> fma(rho, zv, sq1m*zp); outer mul stays.
        const float dWv = FMUL(sqdt, zv);
        const float dWx = FMUL(sqdt, FMA(rho, zv, FMUL(sq1m, zp)));
        // antithetic: exact bitwise negation
        const float dWvB = -dWv;
        const float dWxB = -dWx;

        // ---- path A ----
        {
            const float sv = __fsqrt_rn(fmaxf(vA, 0.0f));
            float r = FMA(alpha0, xA, varphi);
            r = FMA(alpha1, p1A, r);
            r = FMA(Aa0, FSUB(p2A, p3A), r);
            r = FMA(Aa1, p4A, r);
            r = FMA(-c5, p5A, r);
            r = FMA(-c6, p6A, r);
            irA = FMA(r, dt, irA);

            // xn = x - (g*x)*dt + sv*dWx
            const float gx = FMUL(g, xA);
            const float xn = FMA(sv, dWx, FMA(-gx, dt, xA));
            // vn = v + (kappa*(theta-v))*dt + (sigma*sv)*dWv
            const float kv = FMUL(kappa, FSUB(theta, vA));
            const float ss = FMUL(sigma, sv);
            const float vn = FMA(ss, dWv, FMA(kv, dt, vA));
            // pXn = pX + (u - c*pX)*dt : inner fsub(u, mul) -> fma(-c,pX,u); outer fma
            const float t1 = FMA(-g,  p1A, xA);   const float p1n = FMA(t1, dt, p1A);
            const float t2 = FMA(-g,  p2A, vA);   const float p2n = FMA(t2, dt, p2A);
            const float t3 = FMA(-g2, p3A, vA);   const float p3n = FMA(t3, dt, p3A);
            const float t4 = FMA(-g,  p4A, p2A);  const float p4n = FMA(t4, dt, p4A);
            const float t5 = FMA(-g2, p5A, p3A);  const float p5n = FMA(t5, dt, p5A);
            const float p5x2 = FMUL(2.0f, p5A);
            const float t6 = FMA(-g2, p6A, p5x2); const float p6n = FMA(t6, dt, p6A);
            xA = xn; vA = vn;
            p1A = p1n; p2A = p2n; p3A = p3n; p4A = p4n; p5A = p5n; p6A = p6n;
        }

        // ---- path B ----
        {
            const float sv = __fsqrt_rn(fmaxf(vB, 0.0f));
            float r = FMA(alpha0, xB, varphi);
            r = FMA(alpha1, p1B, r);
            r = FMA(Aa0, FSUB(p2B, p3B), r);
            r = FMA(Aa1, p4B, r);
            r = FMA(-c5, p5B, r);
            r = FMA(-c6, p6B, r);
            irB = FMA(r, dt, irB);

            const float gx = FMUL(g, xB);
            const float xn = FMA(sv, dWxB, FMA(-gx, dt, xB));
            const float kv = FMUL(kappa, FSUB(theta, vB));
            const float ss = FMUL(sigma, sv);
            const float vn = FMA(ss, dWvB, FMA(kv, dt, vB));
            const float t1 = FMA(-g,  p1B, xB);   const float p1n = FMA(t1, dt, p1B);
            const float t2 = FMA(-g,  p2B, vB);   const float p2n = FMA(t2, dt, p2B);
            const float t3 = FMA(-g2, p3B, vB);   const float p3n = FMA(t3, dt, p3B);
            const float t4 = FMA(-g,  p4B, p2B);  const float p4n = FMA(t4, dt, p4B);
            const float t5 = FMA(-g2, p5B, p3B);  const float p5n = FMA(t5, dt, p5B);
            const float p5x2 = FMUL(2.0f, p5B);
            const float t6 = FMA(-g2, p6B, p5x2); const float p6n = FMA(t6, dt, p6B);
            xB = xn; vB = vn;
            p1B = p1n; p2B = p2n; p3B = p3n; p4B = p4n; p5B = p5n; p6B = p6n;
        }
    }

    // ---- bond loadings (path-independent, plain rn ops) ----
    const float tau = delta;
    const float e1 = expf(-FMUL(g, tau));
    const float e2 = expf(-FMUL(FMUL(2.0f, g), tau));
    const float Bx = FADD(-A, FMUL(e1, FADD(A, FMUL(Bc, tau))));
    const float B1 = FMUL(Bc, FSUB(e1, 1.0f));
    const float B2 = FMUL(A, Bx);
    const float B4 = FMUL(A, B1);
    const float I0 = __fdiv_rn(FSUB(1.0f, e2), FMUL(2.0f, g));
    const float I1 = __fdiv_rn(FSUB(1.0f, FMUL(e2, FADD(1.0f, FMUL(FMUL(2.0f, g), tau)))),
                               FMUL(4.0f, FMUL(g, g)));
    const float g3 = FMUL(FMUL(g, g), g);
    const float inv4g3 = __fdiv_rn(1.0f, FMUL(4.0f, g3));
    const float I2 = FSUB(inv4g3,
                          FMUL(e2, FADD(FADD(__fdiv_rn(FMUL(tau, tau), FMUL(2.0f, g)),
                                             __fdiv_rn(tau, FMUL(2.0f, FMUL(g, g)))),
                                        inv4g3)));
    const float B3 = FADD(FADD(FMUL(FMUL(alpha0, A), I0), FMUL(c5, I1)), FMUL(c6, I2));
    const float B5 = FADD(FMUL(c5, I0), FMUL(FMUL(2.0f, c6), I1));
    const float B6 = FMUL(c6, I0);

    const float Kt    = __fdiv_rn(1.0f, FADD(1.0f, FMUL(delta, strike)));
    const float scale = FMUL(notional, FADD(1.0f, FMUL(delta, strike)));
    const float nvt   = -FMUL(varphi, tau);

    {
        float logP = FADD(nvt, FMUL(Bx, xA));
        logP = FADD(logP, FMUL(B1, p1A));
        logP = FADD(logP, FMUL(B2, p2A));
        logP = FADD(logP, FMUL(B3, p3A));
        logP = FADD(logP, FMUL(B4, p4A));
        logP = FADD(logP, FMUL(B5, p5A));
        logP = FADD(logP, FMUL(B6, p6A));
        const float pT = expf(logP);
        const float pay = FMUL(scale, fmaxf(FSUB(Kt, pT), 0.0f));
        out[i] = FMUL(pay, expf(-irA));
    }
    {
        float logP = FADD(nvt, FMUL(Bx, xB));
        logP = FADD(logP, FMUL(B1, p1B));
        logP = FADD(logP, FMUL(B2, p2B));
        logP = FADD(logP, FMUL(B3, p3B));
        logP = FADD(logP, FMUL(B4, p4B));
        logP = FADD(logP, FMUL(B5, p5B));
        logP = FADD(logP, FMUL(B6, p6B));
        const float pT = expf(logP);
        const float pay = FMUL(scale, fmaxf(FSUB(Kt, pT), 0.0f));
        out[NH + i] = FMUL(pay, expf(-irB));
    }
}

extern "C" void kernel_launch(void* const* d_in, const int* in_sizes, int n_in,
                              void* d_out, int out_size)
{
    const float* x0  = (const float*)d_in[0];
    const float* v0  = (const float*)d_in[1];
    const float* p10 = (const float*)d_in[2];
    const float* p20 = (const float*)d_in[3];
    const float* p30 = (const float*)d_in[4];
    const float* p40 = (const float*)d_in[5];
    const float* p50 = (const float*)d_in[6];
    const float* p60 = (const float*)d_in[7];
    const float* kappa   = (const float*)d_in[8];
    const float* theta   = (const float*)d_in[9];
    const float* rho     = (const float*)d_in[10];
    const float* sigma   = (const float*)d_in[11];
    const float* alpha0  = (const float*)d_in[12];
    const float* alpha1  = (const float*)d_in[13];
    const float* gamma_  = (const float*)d_in[14];
    const float* varphi  = (const float*)d_in[15];
    const float* strike  = (const float*)d_in[16];
    const float* delta   = (const float*)d_in[17];
    const float* notional= (const float*)d_in[18];
    const float* dt      = (const float*)d_in[19];
    const float* Z       = (const float*)d_in[20];

    const int NH    = in_sizes[0];
    const int STEPS = in_sizes[20] / (2 * NH);

    float* out = (float*)d_out;

    const int threads = 256;
    const int blocks = (NH + threads - 1) / threads;
    cpl_mc_kernel<<<blocks, threads>>>(
        x0, v0, p10, p20, p30, p40, p50, p60,
        kappa, theta, rho, sigma, alpha0, alpha1, gamma_, varphi,
        strike, delta, notional, dt, Z, out, NH, STEPS);
}

// round 4
// speedup vs baseline: 1.2192x; 1.2192x over previous
#include <cuda_runtime.h>
#include <math.h>

// One thread per PATH (2*NH threads). Even thread = +Z leg, odd thread = -Z leg
// of the same antithetic pair, so the duplicate Z reads coalesce inside a warp.
// Z layout: [STEPS][2][NH] float32. Output: [2*NH] (A paths then B paths).
//
// In-loop arithmetic mirrors XLA:GPU's LLVM "contract" FMA formation
// (validated round 3, rel_err 8.6e-6): fma exactly where a single-use mul
// feeds an add/sub; inner muls stay muls; no constant pre-folding.

#define FMUL(a,b) __fmul_rn((a),(b))
#define FADD(a,b) __fadd_rn((a),(b))
#define FSUB(a,b) __fsub_rn((a),(b))
#define FMA(a,b,c) __fmaf_rn((a),(b),(c))

__global__ void __launch_bounds__(256, 4) cpl_mc_kernel(
    const float* __restrict__ x0,  const float* __restrict__ v0,
    const float* __restrict__ p10, const float* __restrict__ p20,
    const float* __restrict__ p30, const float* __restrict__ p40,
    const float* __restrict__ p50, const float* __restrict__ p60,
    const float* __restrict__ s_kappa,  const float* __restrict__ s_theta,
    const float* __restrict__ s_rho,    const float* __restrict__ s_sigma,
    const float* __restrict__ s_alpha0, const float* __restrict__ s_alpha1,
    const float* __restrict__ s_gamma,  const float* __restrict__ s_varphi,
    const float* __restrict__ s_strike, const float* __restrict__ s_delta,
    const float* __restrict__ s_notional, const float* __restrict__ s_dt,
    const float* __restrict__ Z,
    float* __restrict__ out, int NH, int STEPS)
{
    const int p = blockIdx.x * blockDim.x + threadIdx.x;
    if (p >= 2 * NH) return;
    const int  i   = p >> 1;                    // pair index
    const bool neg = (p & 1);                   // odd thread = antithetic leg
    const float sgn = neg ? -1.0f : 1.0f;

    // ---- scalars ----
    const float kappa  = *s_kappa;
    const float theta  = *s_theta;
    const float rho    = *s_rho;
    const float sigma  = *s_sigma;
    const float alpha0 = *s_alpha0;
    const float alpha1 = *s_alpha1;
    const float g      = *s_gamma;
    const float varphi = *s_varphi;
    const float strike = *s_strike;
    const float delta  = *s_delta;
    const float notional = *s_notional;
    const float dt     = *s_dt;

    // ---- derived constants: plain rn ops, exact reference order ----
    const float A  = FADD(__fdiv_rn(alpha0, g), __fdiv_rn(alpha1, FMUL(g, g)));
    const float Bc = __fdiv_rn(alpha1, g);
    const float sq1m = __fsqrt_rn(FSUB(1.0f, FMUL(rho, rho)));
    const float sqdt = __fsqrt_rn(dt);
    const float c5 = FADD(FMUL(alpha0, Bc), FMUL(alpha1, A));
    const float c6 = FMUL(alpha1, Bc);
    const float Aa0 = FMUL(A, alpha0);
    const float Aa1 = FMUL(A, alpha1);
    const float g2  = FMUL(2.0f, g);

    // ---- state ----
    float x  = x0[i];
    float v  = v0[i];
    float p1 = p10[i];
    float p2 = p20[i];
    float p3 = p30[i];
    float p4 = p40[i];
    float p5 = p50[i];
    float p6 = p60[i];
    float ir = 0.0f;

    const size_t stride = (size_t)2 * (size_t)NH;
    const float* zv_ptr = Z + i;
    const float* zp_ptr = Z + (size_t)NH + i;

    #pragma unroll 4
    for (int t = 0; t < STEPS; ++t) {
        // even/odd threads of a warp read the same address -> one coalesced
        // 64B request per warp half; sgn applies the antithetic flip exactly.
        const float zv = FMUL(sgn, __ldcs(zv_ptr));
        const float zp = FMUL(sgn, __ldcs(zp_ptr));
        zv_ptr += stride;
        zp_ptr += stride;

        // dWv = sqdt*zv ; dWx = sqdt*(rho*zv + sq1m*zp)
        const float dWv = FMUL(sqdt, zv);
        const float dWx = FMUL(sqdt, FMA(rho, zv, FMUL(sq1m, zp)));

        const float sv = __fsqrt_rn(fmaxf(v, 0.0f));
        float r = FMA(alpha0, x, varphi);
        r = FMA(alpha1, p1, r);
        r = FMA(Aa0, FSUB(p2, p3), r);
        r = FMA(Aa1, p4, r);
        r = FMA(-c5, p5, r);
        r = FMA(-c6, p6, r);
        ir = FMA(r, dt, ir);

        // xn = x - (g*x)*dt + sv*dWx
        const float gx = FMUL(g, x);
        const float xn = FMA(sv, dWx, FMA(-gx, dt, x));
        // vn = v + (kappa*(theta-v))*dt + (sigma*sv)*dWv
        const float kv = FMUL(kappa, FSUB(theta, v));
        const float ss = FMUL(sigma, sv);
        const float vn = FMA(ss, dWv, FMA(kv, dt, v));
        // pXn = pX + (u - c*pX)*dt
        const float t1 = FMA(-g,  p1, x);    const float p1n = FMA(t1, dt, p1);
        const float t2 = FMA(-g,  p2, v);    const float p2n = FMA(t2, dt, p2);
        const float t3 = FMA(-g2, p3, v);    const float p3n = FMA(t3, dt, p3);
        const float t4 = FMA(-g,  p4, p2);   const float p4n = FMA(t4, dt, p4);
        const float t5 = FMA(-g2, p5, p3);   const float p5n = FMA(t5, dt, p5);
        const float p5x2 = FMUL(2.0f, p5);
        const float t6 = FMA(-g2, p6, p5x2); const float p6n = FMA(t6, dt, p6);
        x = xn; v = vn;
        p1 = p1n; p2 = p2n; p3 = p3n; p4 = p4n; p5 = p5n; p6 = p6n;
    }

    // ---- bond loadings (path-independent, plain rn ops) ----
    const float tau = delta;
    const float e1 = expf(-FMUL(g, tau));
    const float e2 = expf(-FMUL(FMUL(2.0f, g), tau));
    const float Bx = FADD(-A, FMUL(e1, FADD(A, FMUL(Bc, tau))));
    const float B1 = FMUL(Bc, FSUB(e1, 1.0f));
    const float B2 = FMUL(A, Bx);
    const float B4 = FMUL(A, B1);
    const float I0 = __fdiv_rn(FSUB(1.0f, e2), FMUL(2.0f, g));
    const float I1 = __fdiv_rn(FSUB(1.0f, FMUL(e2, FADD(1.0f, FMUL(FMUL(2.0f, g), tau)))),
                               FMUL(4.0f, FMUL(g, g)));
    const float g3 = FMUL(FMUL(g, g), g);
    const float inv4g3 = __fdiv_rn(1.0f, FMUL(4.0f, g3));
    const float I2 = FSUB(inv4g3,
                          FMUL(e2, FADD(FADD(__fdiv_rn(FMUL(tau, tau), FMUL(2.0f, g)),
                                             __fdiv_rn(tau, FMUL(2.0f, FMUL(g, g)))),
                                        inv4g3)));
    const float B3 = FADD(FADD(FMUL(FMUL(alpha0, A), I0), FMUL(c5, I1)), FMUL(c6, I2));
    const float B5 = FADD(FMUL(c5, I0), FMUL(FMUL(2.0f, c6), I1));
    const float B6 = FMUL(c6, I0);

    const float Kt    = __fdiv_rn(1.0f, FADD(1.0f, FMUL(delta, strike)));
    const float scale = FMUL(notional, FADD(1.0f, FMUL(delta, strike)));
    const float nvt   = -FMUL(varphi, tau);

    float logP = FADD(nvt, FMUL(Bx, x));
    logP = FADD(logP, FMUL(B1, p1));
    logP = FADD(logP, FMUL(B2, p2));
    logP = FADD(logP, FMUL(B3, p3));
    logP = FADD(logP, FMUL(B4, p4));
    logP = FADD(logP, FMUL(B5, p5));
    logP = FADD(logP, FMUL(B6, p6));
    const float pT = expf(logP);
    const float pay = FMUL(scale, fmaxf(FSUB(Kt, pT), 0.0f));
    // out layout: [A paths (0..NH-1), B paths (NH..2NH-1)]
    out[(neg ? NH : 0) + i] = FMUL(pay, expf(-ir));
}

extern "C" void kernel_launch(void* const* d_in, const int* in_sizes, int n_in,
                              void* d_out, int out_size)
{
    const float* x0  = (const float*)d_in[0];
    const float* v0  = (const float*)d_in[1];
    const float* p10 = (const float*)d_in[2];
    const float* p20 = (const float*)d_in[3];
    const float* p30 = (const float*)d_in[4];
    const float* p40 = (const float*)d_in[5];
    const float* p50 = (const float*)d_in[6];
    const float* p60 = (const float*)d_in[7];
    const float* kappa   = (const float*)d_in[8];
    const float* theta   = (const float*)d_in[9];
    const float* rho     = (const float*)d_in[10];
    const float* sigma   = (const float*)d_in[11];
    const float* alpha0  = (const float*)d_in[12];
    const float* alpha1  = (const float*)d_in[13];
    const float* gamma_  = (const float*)d_in[14];
    const float* varphi  = (const float*)d_in[15];
    const float* strike  = (const float*)d_in[16];
    const float* delta   = (const float*)d_in[17];
    const float* notional= (const float*)d_in[18];
    const float* dt      = (const float*)d_in[19];
    const float* Z       = (const float*)d_in[20];

    const int NH    = in_sizes[0];
    const int STEPS = in_sizes[20] / (2 * NH);

    float* out = (float*)d_out;

    const int threads = 256;
    const int total   = 2 * NH;
    const int blocks  = (total + threads - 1) / threads;
    cpl_mc_kernel<<<blocks, threads>>>(
        x0, v0, p10, p20, p30, p40, p50, p60,
        kappa, theta, rho, sigma, alpha0, alpha1, gamma_, varphi,
        strike, delta, notional, dt, Z, out, NH, STEPS);
}

// round 6
// speedup vs baseline: 2.3177x; 1.9009x over previous
#include <cuda_runtime.h>
#include <math.h>
#include <stdint.h>

// One thread per PATH (2*NH threads). Even thread = +Z leg, odd thread = -Z
// leg of the same antithetic pair. Z is staged through shared memory with a
// double-buffered cp.async pipeline (chunks of CH steps) so the per-warp
// critical path never waits on DRAM.
//
// In-loop arithmetic mirrors XLA:GPU's LLVM "contract" FMA formation
// (validated round 3, rel_err 8.6e-6): fma exactly where a single-use mul
// feeds an add/sub; inner muls stay muls; no constant pre-folding.
// Antithetic flip is a sign-bit XOR (bitwise identical to mul by -1.0f).

#define FMUL(a,b) __fmul_rn((a),(b))
#define FADD(a,b) __fadd_rn((a),(b))
#define FSUB(a,b) __fsub_rn((a),(b))
#define FMA(a,b,c) __fmaf_rn((a),(b),(c))

#define THREADS 128
#define PAIRS   64          // pairs per block
#define CH      10          // steps per staged chunk (250 % 10 == 0)

__global__ void __launch_bounds__(THREADS, 7) cpl_mc_kernel(
    const float* __restrict__ x0,  const float* __restrict__ v0,
    const float* __restrict__ p10, const float* __restrict__ p20,
    const float* __restrict__ p30, const float* __restrict__ p40,
    const float* __restrict__ p50, const float* __restrict__ p60,
    const float* __restrict__ s_kappa,  const float* __restrict__ s_theta,
    const float* __restrict__ s_rho,    const float* __restrict__ s_sigma,
    const float* __restrict__ s_alpha0, const float* __restrict__ s_alpha1,
    const float* __restrict__ s_gamma,  const float* __restrict__ s_varphi,
    const float* __restrict__ s_strike, const float* __restrict__ s_delta,
    const float* __restrict__ s_notional, const float* __restrict__ s_dt,
    const float* __restrict__ Z,
    float* __restrict__ out, int NH, int STEPS)
{
    __shared__ float zbuf[2][CH][2][PAIRS];

    const int tid   = threadIdx.x;
    const int ibase = blockIdx.x * PAIRS;          // first pair of this block
    const int pair  = tid >> 1;                     // local pair 0..63
    const int i     = ibase + pair;                 // global pair index
    const bool neg  = (tid & 1);
    const uint32_t smask = neg ? 0x80000000u : 0u;  // exact antithetic flip

    // ---- scalars ----
    const float kappa  = *s_kappa;
    const float theta  = *s_theta;
    const float rho    = *s_rho;
    const float sigma  = *s_sigma;
    const float alpha0 = *s_alpha0;
    const float alpha1 = *s_alpha1;
    const float g      = *s_gamma;
    const float varphi = *s_varphi;
    const float strike = *s_strike;
    const float delta  = *s_delta;
    const float notional = *s_notional;
    const float dt     = *s_dt;

    // ---- derived constants: plain rn ops, exact reference order ----
    const float A  = FADD(__fdiv_rn(alpha0, g), __fdiv_rn(alpha1, FMUL(g, g)));
    const float Bc = __fdiv_rn(alpha1, g);
    const float sq1m = __fsqrt_rn(FSUB(1.0f, FMUL(rho, rho)));
    const float sqdt = __fsqrt_rn(dt);
    const float c5 = FADD(FMUL(alpha0, Bc), FMUL(alpha1, A));
    const float c6 = FMUL(alpha1, Bc);
    const float Aa0 = FMUL(A, alpha0);
    const float Aa1 = FMUL(A, alpha1);
    const float g2  = FMUL(2.0f, g);

    // ---- state ----
    float x  = x0[i];
    float v  = v0[i];
    float p1 = p10[i];
    float p2 = p20[i];
    float p3 = p30[i];
    float p4 = p40[i];
    float p5 = p50[i];
    float p6 = p60[i];
    float ir = 0.0f;

    const size_t stride = (size_t)2 * (size_t)NH;
    const int nch = (STEPS + CH - 1) / CH;

    // ---- chunk loader: steps [c*CH, c*CH+len) -> zbuf[buf] via cp.async ----
    auto load_chunk = [&](int c, int buf) {
        const int t0  = c * CH;
        const int len = min(CH, STEPS - t0);
        const int slots = len * 32;                       // 16B slots: len*2*16
        const float* gbase = Z + (size_t)t0 * stride + ibase;
        #pragma unroll
        for (int r = 0; r < (CH * 32 + THREADS - 1) / THREADS; ++r) {
            const int s = tid + r * THREADS;
            if (s < slots) {
                const int k    = s >> 5;
                const int half = (s >> 4) & 1;
                const int q    = (s & 15) << 2;           // float offset
                const float* gp = gbase + (size_t)k * stride + (size_t)half * NH + q;
                const uint32_t sm = (uint32_t)__cvta_generic_to_shared(&zbuf[buf][k][half][q]);
                asm volatile("cp.async.cg.shared.global [%0], [%1], 16;\n"
                             :: "r"(sm), "l"(gp));
            }
        }
    };

    load_chunk(0, 0);
    asm volatile("cp.async.commit_group;\n");

    for (int c = 0; c < nch; ++c) {
        const int cur = c & 1;
        if (c + 1 < nch) {
            load_chunk(c + 1, cur ^ 1);
            asm volatile("cp.async.commit_group;\n");
            asm volatile("cp.async.wait_group 1;\n");
        } else {
            asm volatile("cp.async.wait_group 0;\n");
        }
        __syncthreads();

        const int len = min(CH, STEPS - c * CH);

        #pragma unroll
        for (int k = 0; k < CH; ++k) {
            if (k >= len) break;
            const uint32_t uzv = __float_as_uint(zbuf[cur][k][0][pair]) ^ smask;
            const uint32_t uzp = __float_as_uint(zbuf[cur][k][1][pair]) ^ smask;
            const float zv = __uint_as_float(uzv);
            const float zp = __uint_as_float(uzp);

            // dWv = sqdt*zv ; dWx = sqdt*(rho*zv + sq1m*zp)
            const float dWv = FMUL(sqdt, zv);
            const float dWx = FMUL(sqdt, FMA(rho, zv, FMUL(sq1m, zp)));

            const float sv = __fsqrt_rn(fmaxf(v, 0.0f));
            float r = FMA(alpha0, x, varphi);
            r = FMA(alpha1, p1, r);
            r = FMA(Aa0, FSUB(p2, p3), r);
            r = FMA(Aa1, p4, r);
            r = FMA(-c5, p5, r);
            r = FMA(-c6, p6, r);
            ir = FMA(r, dt, ir);

            // xn = x - (g*x)*dt + sv*dWx
            const float gx = FMUL(g, x);
            const float xn = FMA(sv, dWx, FMA(-gx, dt, x));
            // vn = v + (kappa*(theta-v))*dt + (sigma*sv)*dWv
            const float kv = FMUL(kappa, FSUB(theta, v));
            const float ss = FMUL(sigma, sv);
            const float vn = FMA(ss, dWv, FMA(kv, dt, v));
            // pXn = pX + (u - c*pX)*dt
            const float t1 = FMA(-g,  p1, x);    const float p1n = FMA(t1, dt, p1);
            const float t2 = FMA(-g,  p2, v);    const float p2n = FMA(t2, dt, p2);
            const float t3 = FMA(-g2, p3, v);    const float p3n = FMA(t3, dt, p3);
            const float t4 = FMA(-g,  p4, p2);   const float p4n = FMA(t4, dt, p4);
            const float t5 = FMA(-g2, p5, p3);   const float p5n = FMA(t5, dt, p5);
            const float p5x2 = FMUL(2.0f, p5);
            const float t6 = FMA(-g2, p6, p5x2); const float p6n = FMA(t6, dt, p6);
            x = xn; v = vn;
            p1 = p1n; p2 = p2n; p3 = p3n; p4 = p4n; p5 = p5n; p6 = p6n;
        }
        __syncthreads();   // protect buffer being refilled next iteration
    }

    // ---- bond loadings (path-independent, plain rn ops) ----
    const float tau = delta;
    const float e1 = expf(-FMUL(g, tau));
    const float e2 = expf(-FMUL(FMUL(2.0f, g), tau));
    const float Bx = FADD(-A, FMUL(e1, FADD(A, FMUL(Bc, tau))));
    const float B1 = FMUL(Bc, FSUB(e1, 1.0f));
    const float B2 = FMUL(A, Bx);
    const float B4 = FMUL(A, B1);
    const float I0 = __fdiv_rn(FSUB(1.0f, e2), FMUL(2.0f, g));
    const float I1 = __fdiv_rn(FSUB(1.0f, FMUL(e2, FADD(1.0f, FMUL(FMUL(2.0f, g), tau)))),
                               FMUL(4.0f, FMUL(g, g)));
    const float g3 = FMUL(FMUL(g, g), g);
    const float inv4g3 = __fdiv_rn(1.0f, FMUL(4.0f, g3));
    const float I2 = FSUB(inv4g3,
                          FMUL(e2, FADD(FADD(__fdiv_rn(FMUL(tau, tau), FMUL(2.0f, g)),
                                             __fdiv_rn(tau, FMUL(2.0f, FMUL(g, g)))),
                                        inv4g3)));
    const float B3 = FADD(FADD(FMUL(FMUL(alpha0, A), I0), FMUL(c5, I1)), FMUL(c6, I2));
    const float B5 = FADD(FMUL(c5, I0), FMUL(FMUL(2.0f, c6), I1));
    const float B6 = FMUL(c6, I0);

    const float Kt    = __fdiv_rn(1.0f, FADD(1.0f, FMUL(delta, strike)));
    const float scale = FMUL(notional, FADD(1.0f, FMUL(delta, strike)));
    const float nvt   = -FMUL(varphi, tau);

    float logP = FADD(nvt, FMUL(Bx, x));
    logP = FADD(logP, FMUL(B1, p1));
    logP = FADD(logP, FMUL(B2, p2));
    logP = FADD(logP, FMUL(B3, p3));
    logP = FADD(logP, FMUL(B4, p4));
    logP = FADD(logP, FMUL(B5, p5));
    logP = FADD(logP, FMUL(B6, p6));
    const float pT = expf(logP);
    const float pay = FMUL(scale, fmaxf(FSUB(Kt, pT), 0.0f));
    out[(neg ? NH : 0) + i] = FMUL(pay, expf(-ir));
}

extern "C" void kernel_launch(void* const* d_in, const int* in_sizes, int n_in,
                              void* d_out, int out_size)
{
    const float* x0  = (const float*)d_in[0];
    const float* v0  = (const float*)d_in[1];
    const float* p10 = (const float*)d_in[2];
    const float* p20 = (const float*)d_in[3];
    const float* p30 = (const float*)d_in[4];
    const float* p40 = (const float*)d_in[5];
    const float* p50 = (const float*)d_in[6];
    const float* p60 = (const float*)d_in[7];
    const float* kappa   = (const float*)d_in[8];
    const float* theta   = (const float*)d_in[9];
    const float* rho     = (const float*)d_in[10];
    const float* sigma   = (const float*)d_in[11];
    const float* alpha0  = (const float*)d_in[12];
    const float* alpha1  = (const float*)d_in[13];
    const float* gamma_  = (const float*)d_in[14];
    const float* varphi  = (const float*)d_in[15];
    const float* strike  = (const float*)d_in[16];
    const float* delta   = (const float*)d_in[17];
    const float* notional= (const float*)d_in[18];
    const float* dt      = (const float*)d_in[19];
    const float* Z       = (const float*)d_in[20];

    const int NH    = in_sizes[0];
    const int STEPS = in_sizes[20] / (2 * NH);

    float* out = (float*)d_out;

    const int total  = 2 * NH;
    const int blocks = (total + THREADS - 1) / THREADS;
    cpl_mc_kernel<<<blocks, THREADS>>>(
        x0, v0, p10, p20, p30, p40, p50, p60,
        kappa, theta, rho, sigma, alpha0, alpha1, gamma_, varphi,
        strike, delta, notional, dt, Z, out, NH, STEPS);
}